// round 2
// baseline (speedup 1.0000x reference)
#include <cuda_runtime.h>
#include <math.h>

// Problem dims
#define BATCH 4096
#define HID   1024
#define INF   2048           // input features of the fused GEMM (input + hidden)
#define GATES 4096           // 4 * HID

// ---------------- device scratch (static; no allocations) ----------------
__device__ float g_xh[BATCH * INF];      // 32 MB  concat(input, hx)
__device__ float g_w [GATES * INF];      // 32 MB  concat(Wi, Wf, Wg, Wo) rows
__device__ float g_gates[(size_t)BATCH * GATES];  // 64 MB pre-activation gates

// ---------------- pack kernels ----------------
__global__ void pack_xh_kernel(const float* __restrict__ inp,
                               const float* __restrict__ hx) {
    int idx  = blockIdx.x * blockDim.x + threadIdx.x;   // float4 index
    int elem = idx * 4;
    if (elem >= BATCH * INF) return;
    int b = elem >> 11;          // / 2048
    int k = elem & 2047;
    float4 v;
    if (k < HID) v = *(const float4*)(inp + (size_t)b * HID + k);
    else         v = *(const float4*)(hx  + (size_t)b * HID + (k - HID));
    *(float4*)(g_xh + elem) = v;
}

__global__ void pack_w_kernel(const float* __restrict__ Wi,
                              const float* __restrict__ Wf,
                              const float* __restrict__ Wg,
                              const float* __restrict__ Wo) {
    int idx  = blockIdx.x * blockDim.x + threadIdx.x;   // float4 index
    long elem = (long)idx * 4;
    if (elem >= (long)GATES * INF) return;
    int j = (int)(elem >> 11);   // output row 0..4095
    int k = (int)(elem & 2047);
    int gate = j >> 10;
    int r    = j & 1023;
    const float* W = (gate == 0) ? Wi : (gate == 1) ? Wf : (gate == 2) ? Wg : Wo;
    *(float4*)(g_w + elem) = *(const float4*)(W + (long)r * INF + k);
}

// ---------------- GEMM: gates = xh @ Wcat^T ----------------
// C[4096, 4096] = A[4096, 2048] * B^T, B = g_w rows (each row = one output col)
#define BM 128
#define BN 128
#define BK 16
#define TM 8
#define TN 8

__global__ __launch_bounds__(256) void gemm_kernel() {
    __shared__ float As[BK][BM];
    __shared__ float Bs[BK][BN];

    const int tid  = threadIdx.x;
    const int ty   = tid >> 4;        // 0..15
    const int tx   = tid & 15;        // 0..15
    const int brow = blockIdx.y;      // batch tile
    const int bcol = blockIdx.x;      // gate-col tile

    const float* A = g_xh + (size_t)brow * BM * INF;
    const float* B = g_w  + (size_t)bcol * BN * INF;

    float acc[TM][TN];
    #pragma unroll
    for (int i = 0; i < TM; i++)
        #pragma unroll
        for (int j = 0; j < TN; j++) acc[i][j] = 0.f;

    // tile load mapping: BMxBK = 2048 floats = 512 float4; 256 thr -> 2 each
    // float4 index f: row = f>>2, kc = (f&3)*4
    for (int kt = 0; kt < INF; kt += BK) {
        #pragma unroll
        for (int l = 0; l < 2; l++) {
            int f   = tid + l * 256;
            int row = f >> 2;
            int kc  = (f & 3) << 2;
            float4 av = *(const float4*)(A + (size_t)row * INF + kt + kc);
            As[kc + 0][row] = av.x;
            As[kc + 1][row] = av.y;
            As[kc + 2][row] = av.z;
            As[kc + 3][row] = av.w;
            float4 bv = *(const float4*)(B + (size_t)row * INF + kt + kc);
            Bs[kc + 0][row] = bv.x;
            Bs[kc + 1][row] = bv.y;
            Bs[kc + 2][row] = bv.z;
            Bs[kc + 3][row] = bv.w;
        }
        __syncthreads();

        #pragma unroll
        for (int k = 0; k < BK; k++) {
            float ar[TM], br[TN];
            #pragma unroll
            for (int i = 0; i < TM; i++) ar[i] = As[k][ty * TM + i];
            #pragma unroll
            for (int j = 0; j < TN; j++) br[j] = Bs[k][tx * TN + j];
            #pragma unroll
            for (int i = 0; i < TM; i++)
                #pragma unroll
                for (int j = 0; j < TN; j++)
                    acc[i][j] = fmaf(ar[i], br[j], acc[i][j]);
        }
        __syncthreads();
    }

    // write back (float4 per 4 cols)
    const int crow0 = brow * BM + ty * TM;
    const int ccol0 = bcol * BN + tx * TN;
    #pragma unroll
    for (int i = 0; i < TM; i++) {
        float* out = g_gates + (size_t)(crow0 + i) * GATES + ccol0;
        #pragma unroll
        for (int j = 0; j < TN; j += 4) {
            float4 v = make_float4(acc[i][j], acc[i][j+1], acc[i][j+2], acc[i][j+3]);
            *(float4*)(out + j) = v;
        }
    }
}

// ---------------- fused epilogue ----------------
__device__ __forceinline__ float sigmoidf_(float x) {
    return 1.f / (1.f + expf(-x));
}

__global__ void epilogue_kernel(const float* __restrict__ cx,
                                const float* __restrict__ bi,
                                const float* __restrict__ bf,
                                const float* __restrict__ bg,
                                const float* __restrict__ bo,
                                float* __restrict__ out) {
    int idx = blockIdx.x * blockDim.x + threadIdx.x;   // over BATCH*HID
    if (idx >= BATCH * HID) return;
    int b = idx >> 10;
    int h = idx & 1023;
    const float* grow = g_gates + (size_t)b * GATES;
    float i_t = grow[h]           + bi[h];
    float f_t = grow[HID + h]     + bf[h];
    float g_t = grow[2 * HID + h] + bg[h];
    float o_t = grow[3 * HID + h] + bo[h];
    i_t = sigmoidf_(i_t);
    f_t = sigmoidf_(f_t);
    g_t = tanhf(g_t);
    o_t = sigmoidf_(o_t);
    float c_new = f_t * cx[idx] + i_t * g_t;
    float h_new = o_t * tanhf(c_new);
    out[idx] = h_new;                     // h_new first
    out[BATCH * HID + idx] = c_new;       // then c_new
}

// ---------------- launch ----------------
extern "C" void kernel_launch(void* const* d_in, const int* in_sizes, int n_in,
                              void* d_out, int out_size) {
    const float* input = (const float*)d_in[0];
    const float* hx    = (const float*)d_in[1];
    const float* cx    = (const float*)d_in[2];
    const float* Wi    = (const float*)d_in[3];
    const float* bi    = (const float*)d_in[4];
    const float* Wf    = (const float*)d_in[5];
    const float* bf    = (const float*)d_in[6];
    const float* Wg    = (const float*)d_in[7];
    const float* bg    = (const float*)d_in[8];
    const float* Wo    = (const float*)d_in[9];
    const float* bo    = (const float*)d_in[10];
    float* out = (float*)d_out;

    // pack concat(input, hx) -> g_xh
    {
        int n4 = (BATCH * INF) / 4;
        pack_xh_kernel<<<(n4 + 255) / 256, 256>>>(input, hx);
    }
    // pack concat(Wi,Wf,Wg,Wo) -> g_w
    {
        int n4 = (GATES * INF) / 4;
        pack_w_kernel<<<(n4 + 255) / 256, 256>>>(Wi, Wf, Wg, Wo);
    }
    // GEMM
    {
        dim3 grid(GATES / BN, BATCH / BM);
        gemm_kernel<<<grid, 256>>>();
    }
    // epilogue
    {
        int n = BATCH * HID;
        epilogue_kernel<<<(n + 255) / 256, 256>>>(cx, bi, bf, bg, bo, out);
    }
}

// round 4
// speedup vs baseline: 2.6263x; 2.6263x over previous
#include <cuda_runtime.h>
#include <cuda_bf16.h>
#include <math.h>
#include <stdint.h>

// Problem dims
#define BATCH 4096
#define HID   1024
#define INF   2048           // input + hidden
#define GATES 4096           // 4*HID

// GEMM tiling
#define BM 128
#define BN 128
#define KC 64                // K elems per stage (128B bf16 rows, SW128)
#define NSTAGE 3
#define NKIT (INF / KC)      // 32

#define TILE_BYTES  (128 * 128)          // one 128-row x 128B tile
#define STAGE_BYTES (4 * TILE_BYTES)     // Ahi, Alo, Bhi, Blo
#define SMEM_TOTAL  (NSTAGE * STAGE_BYTES)   // 196608

static __device__ __forceinline__ uint32_t sw128(uint32_t o) {
    return o ^ ((o >> 3) & 0x70);
}
static __device__ __forceinline__ uint32_t smem_u32(const void* p) {
    uint32_t a;
    asm("{ .reg .u64 t; cvta.to.shared.u64 t, %1; cvt.u32.u64 %0, t; }" : "=r"(a) : "l"(p));
    return a;
}

#define CP_ASYNC16(dst, src) \
    asm volatile("cp.async.cg.shared.global [%0], [%1], 16;" :: "r"(dst), "l"(src))
#define CP_COMMIT() asm volatile("cp.async.commit_group;" ::: "memory")
#define CP_WAIT2()  asm volatile("cp.async.wait_group 2;" ::: "memory")
#define CP_WAIT0()  asm volatile("cp.async.wait_group 0;" ::: "memory")

#define LDMX4(r0, r1, r2, r3, a) \
    asm volatile("ldmatrix.sync.aligned.m8n8.x4.shared.b16 {%0,%1,%2,%3}, [%4];" \
                 : "=r"(r0), "=r"(r1), "=r"(r2), "=r"(r3) : "r"(a))

#define MMA_BF16(d, a, b0, b1) \
    asm volatile("mma.sync.aligned.m16n8k16.row.col.f32.bf16.bf16.f32 " \
                 "{%0,%1,%2,%3}, {%4,%5,%6,%7}, {%8,%9}, {%0,%1,%2,%3};" \
                 : "+f"(d[0]), "+f"(d[1]), "+f"(d[2]), "+f"(d[3]) \
                 : "r"(a[0]), "r"(a[1]), "r"(a[2]), "r"(a[3]), "r"(b0), "r"(b1))

// ---------------- device scratch (bf16 hi/lo split) ----------------
__device__ __nv_bfloat16 g_xh_hi[(size_t)BATCH * INF];
__device__ __nv_bfloat16 g_xh_lo[(size_t)BATCH * INF];
__device__ __nv_bfloat16 g_w_hi[(size_t)GATES * INF];   // row j = h*4 + gate
__device__ __nv_bfloat16 g_w_lo[(size_t)GATES * INF];

// ---------------- pack kernels ----------------
__global__ void pack_xh_kernel(const float* __restrict__ inp,
                               const float* __restrict__ hx) {
    int idx = blockIdx.x * blockDim.x + threadIdx.x;   // float4 index
    int elem = idx * 4;
    if (elem >= BATCH * INF) return;
    int b = elem >> 11;
    int k = elem & 2047;
    float4 v;
    if (k < HID) v = *(const float4*)(inp + (size_t)b * HID + k);
    else         v = *(const float4*)(hx  + (size_t)b * HID + (k - HID));
    float x[4] = {v.x, v.y, v.z, v.w};
    __nv_bfloat16 hi[4], lo[4];
    #pragma unroll
    for (int i = 0; i < 4; i++) {
        hi[i] = __float2bfloat16_rn(x[i]);
        lo[i] = __float2bfloat16_rn(x[i] - __bfloat162float(hi[i]));
    }
    *(uint64_t*)(g_xh_hi + elem) = *(uint64_t*)hi;
    *(uint64_t*)(g_xh_lo + elem) = *(uint64_t*)lo;
}

__global__ void pack_w_kernel(const float* __restrict__ Wi,
                              const float* __restrict__ Wf,
                              const float* __restrict__ Wg,
                              const float* __restrict__ Wo) {
    int idx = blockIdx.x * blockDim.x + threadIdx.x;   // float4 index
    long elem = (long)idx * 4;
    if (elem >= (long)GATES * INF) return;
    int j = (int)(elem >> 11);      // dest row = h*4 + gate
    int k = (int)(elem & 2047);
    int gate = j & 3;
    int h    = j >> 2;
    const float* W = (gate == 0) ? Wi : (gate == 1) ? Wf : (gate == 2) ? Wg : Wo;
    float4 v = *(const float4*)(W + (long)h * INF + k);
    float x[4] = {v.x, v.y, v.z, v.w};
    __nv_bfloat16 hi[4], lo[4];
    #pragma unroll
    for (int i = 0; i < 4; i++) {
        hi[i] = __float2bfloat16_rn(x[i]);
        lo[i] = __float2bfloat16_rn(x[i] - __bfloat162float(hi[i]));
    }
    *(uint64_t*)(g_w_hi + elem) = *(uint64_t*)hi;
    *(uint64_t*)(g_w_lo + elem) = *(uint64_t*)lo;
}

// ---------------- stage loader (cp.async, SW128 swizzled) ----------------
__device__ __forceinline__ void load_stage(uint32_t stage_base, int brow, int bcol,
                                           int kt, int tid) {
    const char* gA_hi = (const char*)g_xh_hi + (size_t)brow * 128 * 4096 + (size_t)kt * 2;
    const char* gA_lo = (const char*)g_xh_lo + (size_t)brow * 128 * 4096 + (size_t)kt * 2;
    const char* gB_hi = (const char*)g_w_hi  + (size_t)bcol * 128 * 4096 + (size_t)kt * 2;
    const char* gB_lo = (const char*)g_w_lo  + (size_t)bcol * 128 * 4096 + (size_t)kt * 2;
    const char* gsrc[4] = {gA_hi, gA_lo, gB_hi, gB_lo};
    #pragma unroll
    for (int t = 0; t < 4; t++) {
        uint32_t tile_base = stage_base + t * TILE_BYTES;
        #pragma unroll
        for (int rep = 0; rep < 4; rep++) {
            int i = rep * 256 + tid;           // 0..1023
            int row = i >> 3;
            int ch  = (i & 7) * 16;
            uint32_t so = sw128((uint32_t)(row * 128 + ch));
            CP_ASYNC16(tile_base + so, gsrc[t] + (size_t)row * 4096 + ch);
        }
    }
    CP_COMMIT();
}

// ---------------- fused GEMM (mma.sync bf16 x3) + LSTM epilogue ----------------
__global__ __launch_bounds__(256, 1) void lstm_gemm_kernel(
    const float* __restrict__ cx,
    const float* __restrict__ bi, const float* __restrict__ bf_,
    const float* __restrict__ bg, const float* __restrict__ bo,
    float* __restrict__ out)
{
    extern __shared__ char smem[];
    const uint32_t sbase = smem_u32(smem);
    const int tid  = threadIdx.x;
    const int wid  = tid >> 5;
    const int lane = tid & 31;
    const int bcol = blockIdx.x;   // 0..31 over gate-cols
    const int brow = blockIdx.y;   // 0..31 over batch

    const int warpM = wid & 1;     // 0..1 -> rows warpM*64
    const int warpN = wid >> 1;    // 0..3 -> cols warpN*32

    // per-lane swizzled base offsets for ldmatrix
    // A: 16-row group at (warpM*64 + mfrag*16); lanes 0-15 rows, 16-31 rows + byte16
    const uint32_t offA = (uint32_t)((warpM * 64 + (lane & 15)) * 128 + (lane >> 4) * 16);
    const uint32_t sbA  = sw128(offA);
    // B: 16-row group at (warpN*32 + nfrag2*16)
    const uint32_t offB = (uint32_t)((warpN * 32 + (lane & 15)) * 128 + (lane >> 4) * 16);
    const uint32_t sbB  = sw128(offB);

    float acc[4][4][4];   // [mfrag][nfrag][4]
    #pragma unroll
    for (int m = 0; m < 4; m++)
        #pragma unroll
        for (int n = 0; n < 4; n++)
            #pragma unroll
            for (int e = 0; e < 4; e++) acc[m][n][e] = 0.f;

    // prologue
    #pragma unroll
    for (int p = 0; p < NSTAGE; p++)
        load_stage(sbase + p * STAGE_BYTES, brow, bcol, p * KC, tid);

    for (int it = 0; it < NKIT; it++) {
        const int slot = it % NSTAGE;
        const uint32_t stg  = sbase + slot * STAGE_BYTES;
        const uint32_t tAh = stg;
        const uint32_t tAl = stg + TILE_BYTES;
        const uint32_t tBh = stg + 2 * TILE_BYTES;
        const uint32_t tBl = stg + 3 * TILE_BYTES;

        if (it < NKIT - 2) CP_WAIT2(); else CP_WAIT0();
        __syncthreads();

        #pragma unroll
        for (int kf = 0; kf < 4; kf++) {
            const uint32_t kx = (uint32_t)(kf * 32);
            uint32_t ah[4][4], al[4][4], bh[4][2], bl[4][2];
            #pragma unroll
            for (int m = 0; m < 4; m++) {
                uint32_t aoff = (uint32_t)(m * 2048);
                LDMX4(ah[m][0], ah[m][1], ah[m][2], ah[m][3], (tAh + sbA + aoff) ^ kx);
                LDMX4(al[m][0], al[m][1], al[m][2], al[m][3], (tAl + sbA + aoff) ^ kx);
            }
            #pragma unroll
            for (int g = 0; g < 2; g++) {      // n-row groups of 16 -> 2 nfrags each
                uint32_t boff = (uint32_t)(g * 2048);
                uint32_t r0, r1, r2, r3;
                LDMX4(r0, r1, r2, r3, (tBh + sbB + boff) ^ kx);
                bh[g * 2 + 0][0] = r0; bh[g * 2 + 0][1] = r2;
                bh[g * 2 + 1][0] = r1; bh[g * 2 + 1][1] = r3;
                LDMX4(r0, r1, r2, r3, (tBl + sbB + boff) ^ kx);
                bl[g * 2 + 0][0] = r0; bl[g * 2 + 0][1] = r2;
                bl[g * 2 + 1][0] = r1; bl[g * 2 + 1][1] = r3;
            }
            #pragma unroll
            for (int m = 0; m < 4; m++)
                #pragma unroll
                for (int n = 0; n < 4; n++) {
                    MMA_BF16(acc[m][n], ah[m], bh[n][0], bh[n][1]);
                    MMA_BF16(acc[m][n], ah[m], bl[n][0], bl[n][1]);
                    MMA_BF16(acc[m][n], al[m], bh[n][0], bh[n][1]);
                }
        }

        __syncthreads();
        if (it + NSTAGE < NKIT)
            load_stage(stg, brow, bcol, (it + NSTAGE) * KC, tid);
    }

    // ---- dump accumulators to smem (fp32 128x128 tile, 64KB) ----
    __syncthreads();
    float* Cs = (float*)smem;
    #pragma unroll
    for (int m = 0; m < 4; m++) {
        const int row = warpM * 64 + m * 16 + (lane >> 2);
        #pragma unroll
        for (int n = 0; n < 4; n++) {
            const int col = warpN * 32 + n * 8 + (lane & 3) * 2;
            *(float2*)&Cs[row * 128 + col]       = make_float2(acc[m][n][0], acc[m][n][1]);
            *(float2*)&Cs[(row + 8) * 128 + col] = make_float2(acc[m][n][2], acc[m][n][3]);
        }
    }
    __syncthreads();

    // ---- fused LSTM epilogue: cols 4*hl + {i,f,g,o} ----
    #pragma unroll
    for (int r = 0; r < 16; r++) {
        const int idx = r * 256 + tid;          // 0..4095 over (row, hl)
        const int row = idx >> 5;
        const int hl  = idx & 31;
        float4 g4 = *(float4*)&Cs[row * 128 + hl * 4];
        const int h = bcol * 32 + hl;
        const int b = brow * 128 + row;
        float i_t = g4.x + bi[h];
        float f_t = g4.y + bf_[h];
        float g_t = g4.z + bg[h];
        float o_t = g4.w + bo[h];
        i_t = 1.f / (1.f + expf(-i_t));
        f_t = 1.f / (1.f + expf(-f_t));
        g_t = tanhf(g_t);
        o_t = 1.f / (1.f + expf(-o_t));
        float c_new = f_t * cx[(size_t)b * HID + h] + i_t * g_t;
        float h_new = o_t * tanhf(c_new);
        out[(size_t)b * HID + h] = h_new;
        out[(size_t)BATCH * HID + (size_t)b * HID + h] = c_new;
    }
}

// ---------------- launch ----------------
extern "C" void kernel_launch(void* const* d_in, const int* in_sizes, int n_in,
                              void* d_out, int out_size) {
    const float* input = (const float*)d_in[0];
    const float* hx    = (const float*)d_in[1];
    const float* cx    = (const float*)d_in[2];
    const float* Wi    = (const float*)d_in[3];
    const float* bi    = (const float*)d_in[4];
    const float* Wf    = (const float*)d_in[5];
    const float* bf    = (const float*)d_in[6];
    const float* Wg    = (const float*)d_in[7];
    const float* bg    = (const float*)d_in[8];
    const float* Wo    = (const float*)d_in[9];
    const float* bo    = (const float*)d_in[10];
    float* out = (float*)d_out;

    static bool attr_set = false;
    if (!attr_set) {
        cudaFuncSetAttribute(lstm_gemm_kernel,
                             cudaFuncAttributeMaxDynamicSharedMemorySize, SMEM_TOTAL);
        attr_set = true;
    }

    {
        int n4 = (BATCH * INF) / 4;
        pack_xh_kernel<<<(n4 + 255) / 256, 256>>>(input, hx);
    }
    {
        int n4 = (GATES * INF) / 4;
        pack_w_kernel<<<(n4 + 255) / 256, 256>>>(Wi, Wf, Wg, Wo);
    }
    {
        dim3 grid(GATES / BN, BATCH / BM);
        lstm_gemm_kernel<<<grid, 256, SMEM_TOTAL>>>(cx, bi, bf, bg, bo, out);
    }
}

// round 5
// speedup vs baseline: 2.8821x; 1.0974x over previous
#include <cuda_runtime.h>
#include <cuda_bf16.h>
#include <math.h>
#include <stdint.h>

// Problem dims
#define BATCH 4096
#define HID   1024
#define INF   2048           // input + hidden
#define GATES 4096           // 4*HID

// GEMM tiling
#define BM 128
#define BN 128
#define KC 64                // K elems per stage (128B bf16 rows, SW128)
#define NSTAGE 3
#define NKIT (INF / KC)      // 32
#define NTHREADS 512

#define TILE_BYTES  (128 * 128)          // one 128-row x 128B tile
#define STAGE_BYTES (4 * TILE_BYTES)     // Ahi, Alo, Bhi, Blo
#define SMEM_TOTAL  (NSTAGE * STAGE_BYTES)   // 196608

static __device__ __forceinline__ uint32_t sw128(uint32_t o) {
    return o ^ ((o >> 3) & 0x70);
}
static __device__ __forceinline__ uint32_t smem_u32(const void* p) {
    uint32_t a;
    asm("{ .reg .u64 t; cvta.to.shared.u64 t, %1; cvt.u32.u64 %0, t; }" : "=r"(a) : "l"(p));
    return a;
}

#define CP_ASYNC16(dst, src) \
    asm volatile("cp.async.cg.shared.global [%0], [%1], 16;" :: "r"(dst), "l"(src))
#define CP_COMMIT() asm volatile("cp.async.commit_group;" ::: "memory")
#define CP_WAIT2()  asm volatile("cp.async.wait_group 2;" ::: "memory")
#define CP_WAIT0()  asm volatile("cp.async.wait_group 0;" ::: "memory")

#define LDMX4(r0, r1, r2, r3, a) \
    asm volatile("ldmatrix.sync.aligned.m8n8.x4.shared.b16 {%0,%1,%2,%3}, [%4];" \
                 : "=r"(r0), "=r"(r1), "=r"(r2), "=r"(r3) : "r"(a))

#define MMA_BF16(d, a, b0, b1) \
    asm volatile("mma.sync.aligned.m16n8k16.row.col.f32.bf16.bf16.f32 " \
                 "{%0,%1,%2,%3}, {%4,%5,%6,%7}, {%8,%9}, {%0,%1,%2,%3};" \
                 : "+f"(d[0]), "+f"(d[1]), "+f"(d[2]), "+f"(d[3]) \
                 : "r"(a[0]), "r"(a[1]), "r"(a[2]), "r"(a[3]), "r"(b0), "r"(b1))

// ---------------- device scratch (bf16 hi/lo split) ----------------
__device__ __nv_bfloat16 g_xh_hi[(size_t)BATCH * INF];
__device__ __nv_bfloat16 g_xh_lo[(size_t)BATCH * INF];
__device__ __nv_bfloat16 g_w_hi[(size_t)GATES * INF];   // row j = h*4 + gate
__device__ __nv_bfloat16 g_w_lo[(size_t)GATES * INF];

// ---------------- pack kernels ----------------
__global__ void pack_xh_kernel(const float* __restrict__ inp,
                               const float* __restrict__ hx) {
    int idx = blockIdx.x * blockDim.x + threadIdx.x;   // float4 index
    int elem = idx * 4;
    if (elem >= BATCH * INF) return;
    int b = elem >> 11;
    int k = elem & 2047;
    float4 v;
    if (k < HID) v = *(const float4*)(inp + (size_t)b * HID + k);
    else         v = *(const float4*)(hx  + (size_t)b * HID + (k - HID));
    float x[4] = {v.x, v.y, v.z, v.w};
    __nv_bfloat16 hi[4], lo[4];
    #pragma unroll
    for (int i = 0; i < 4; i++) {
        hi[i] = __float2bfloat16_rn(x[i]);
        lo[i] = __float2bfloat16_rn(x[i] - __bfloat162float(hi[i]));
    }
    *(uint64_t*)(g_xh_hi + elem) = *(uint64_t*)hi;
    *(uint64_t*)(g_xh_lo + elem) = *(uint64_t*)lo;
}

__global__ void pack_w_kernel(const float* __restrict__ Wi,
                              const float* __restrict__ Wf,
                              const float* __restrict__ Wg,
                              const float* __restrict__ Wo) {
    int idx = blockIdx.x * blockDim.x + threadIdx.x;   // float4 index
    long elem = (long)idx * 4;
    if (elem >= (long)GATES * INF) return;
    int j = (int)(elem >> 11);      // dest row = h*4 + gate
    int k = (int)(elem & 2047);
    int gate = j & 3;
    int h    = j >> 2;
    const float* W = (gate == 0) ? Wi : (gate == 1) ? Wf : (gate == 2) ? Wg : Wo;
    float4 v = *(const float4*)(W + (long)h * INF + k);
    float x[4] = {v.x, v.y, v.z, v.w};
    __nv_bfloat16 hi[4], lo[4];
    #pragma unroll
    for (int i = 0; i < 4; i++) {
        hi[i] = __float2bfloat16_rn(x[i]);
        lo[i] = __float2bfloat16_rn(x[i] - __bfloat162float(hi[i]));
    }
    *(uint64_t*)(g_w_hi + elem) = *(uint64_t*)hi;
    *(uint64_t*)(g_w_lo + elem) = *(uint64_t*)lo;
}

// ---------------- stage loader (cp.async, SW128 swizzled) ----------------
__device__ __forceinline__ void load_stage(uint32_t stage_base, int brow, int bcol,
                                           int kt, int tid) {
    const char* gA_hi = (const char*)g_xh_hi + (size_t)brow * 128 * 4096 + (size_t)kt * 2;
    const char* gA_lo = (const char*)g_xh_lo + (size_t)brow * 128 * 4096 + (size_t)kt * 2;
    const char* gB_hi = (const char*)g_w_hi  + (size_t)bcol * 128 * 4096 + (size_t)kt * 2;
    const char* gB_lo = (const char*)g_w_lo  + (size_t)bcol * 128 * 4096 + (size_t)kt * 2;
    const char* gsrc[4] = {gA_hi, gA_lo, gB_hi, gB_lo};
    #pragma unroll
    for (int t = 0; t < 4; t++) {
        uint32_t tile_base = stage_base + t * TILE_BYTES;
        #pragma unroll
        for (int rep = 0; rep < 2; rep++) {
            int i = rep * NTHREADS + tid;      // 0..1023
            int row = i >> 3;
            int ch  = (i & 7) * 16;
            uint32_t so = sw128((uint32_t)(row * 128 + ch));
            CP_ASYNC16(tile_base + so, gsrc[t] + (size_t)row * 4096 + ch);
        }
    }
    CP_COMMIT();
}

// ---------------- fused GEMM (mma.sync bf16 x3) + LSTM epilogue ----------------
__global__ __launch_bounds__(NTHREADS, 1) void lstm_gemm_kernel(
    const float* __restrict__ cx,
    const float* __restrict__ bi, const float* __restrict__ bf_,
    const float* __restrict__ bg, const float* __restrict__ bo,
    float* __restrict__ out)
{
    extern __shared__ char smem[];
    const uint32_t sbase = smem_u32(smem);
    const int tid  = threadIdx.x;
    const int wid  = tid >> 5;
    const int lane = tid & 31;
    const int bcol = blockIdx.x;   // 0..31 over gate-cols
    const int brow = blockIdx.y;   // 0..31 over batch

    const int warpM = wid & 3;     // 0..3 -> rows warpM*32
    const int warpN = wid >> 2;    // 0..3 -> cols warpN*32

    // per-lane swizzled base offsets for ldmatrix
    const uint32_t offA = (uint32_t)((warpM * 32 + (lane & 15)) * 128 + (lane >> 4) * 16);
    const uint32_t sbA  = sw128(offA);
    const uint32_t offB = (uint32_t)((warpN * 32 + (lane & 15)) * 128 + (lane >> 4) * 16);
    const uint32_t sbB  = sw128(offB);

    float acc[2][4][4];   // [mfrag][nfrag][4]
    #pragma unroll
    for (int m = 0; m < 2; m++)
        #pragma unroll
        for (int n = 0; n < 4; n++)
            #pragma unroll
            for (int e = 0; e < 4; e++) acc[m][n][e] = 0.f;

    // prologue
    #pragma unroll
    for (int p = 0; p < NSTAGE; p++)
        load_stage(sbase + p * STAGE_BYTES, brow, bcol, p * KC, tid);

    for (int it = 0; it < NKIT; it++) {
        const int slot = it % NSTAGE;
        const uint32_t stg  = sbase + slot * STAGE_BYTES;
        const uint32_t tAh = stg;
        const uint32_t tAl = stg + TILE_BYTES;
        const uint32_t tBh = stg + 2 * TILE_BYTES;
        const uint32_t tBl = stg + 3 * TILE_BYTES;

        if (it < NKIT - 2) CP_WAIT2(); else CP_WAIT0();
        __syncthreads();

        #pragma unroll
        for (int kf = 0; kf < 4; kf++) {
            const uint32_t kx = (uint32_t)(kf * 32);
            uint32_t ah[2][4], al[2][4], bh[4][2], bl[4][2];
            #pragma unroll
            for (int m = 0; m < 2; m++) {
                uint32_t aoff = (uint32_t)(m * 2048);   // 16 rows * 128B
                LDMX4(ah[m][0], ah[m][1], ah[m][2], ah[m][3], (tAh + sbA + aoff) ^ kx);
                LDMX4(al[m][0], al[m][1], al[m][2], al[m][3], (tAl + sbA + aoff) ^ kx);
            }
            #pragma unroll
            for (int g = 0; g < 2; g++) {      // two 16-col groups -> 4 nfrags
                uint32_t boff = (uint32_t)(g * 2048);
                uint32_t r0, r1, r2, r3;
                LDMX4(r0, r1, r2, r3, (tBh + sbB + boff) ^ kx);
                bh[g * 2 + 0][0] = r0; bh[g * 2 + 0][1] = r2;
                bh[g * 2 + 1][0] = r1; bh[g * 2 + 1][1] = r3;
                LDMX4(r0, r1, r2, r3, (tBl + sbB + boff) ^ kx);
                bl[g * 2 + 0][0] = r0; bl[g * 2 + 0][1] = r2;
                bl[g * 2 + 1][0] = r1; bl[g * 2 + 1][1] = r3;
            }
            #pragma unroll
            for (int m = 0; m < 2; m++)
                #pragma unroll
                for (int n = 0; n < 4; n++) {
                    MMA_BF16(acc[m][n], ah[m], bh[n][0], bh[n][1]);
                    MMA_BF16(acc[m][n], ah[m], bl[n][0], bl[n][1]);
                    MMA_BF16(acc[m][n], al[m], bh[n][0], bh[n][1]);
                }
        }

        __syncthreads();
        if (it + NSTAGE < NKIT)
            load_stage(stg, brow, bcol, (it + NSTAGE) * KC, tid);
    }

    // ---- dump accumulators to smem (fp32 128x128 tile, 64KB) ----
    __syncthreads();
    float* Cs = (float*)smem;
    #pragma unroll
    for (int m = 0; m < 2; m++) {
        const int row = warpM * 32 + m * 16 + (lane >> 2);
        #pragma unroll
        for (int n = 0; n < 4; n++) {
            const int col = warpN * 32 + n * 8 + (lane & 3) * 2;
            *(float2*)&Cs[row * 128 + col]       = make_float2(acc[m][n][0], acc[m][n][1]);
            *(float2*)&Cs[(row + 8) * 128 + col] = make_float2(acc[m][n][2], acc[m][n][3]);
        }
    }
    __syncthreads();

    // ---- fused LSTM epilogue: cols 4*hl + {i,f,g,o} ----
    #pragma unroll
    for (int r = 0; r < 8; r++) {
        const int idx = r * NTHREADS + tid;     // 0..4095 over (row, hl)
        const int row = idx >> 5;
        const int hl  = idx & 31;
        float4 g4 = *(float4*)&Cs[row * 128 + hl * 4];
        const int h = bcol * 32 + hl;
        const int b = brow * 128 + row;
        float i_t = g4.x + bi[h];
        float f_t = g4.y + bf_[h];
        float g_t = g4.z + bg[h];
        float o_t = g4.w + bo[h];
        i_t = 1.f / (1.f + expf(-i_t));
        f_t = 1.f / (1.f + expf(-f_t));
        g_t = tanhf(g_t);
        o_t = 1.f / (1.f + expf(-o_t));
        float c_new = f_t * cx[(size_t)b * HID + h] + i_t * g_t;
        float h_new = o_t * tanhf(c_new);
        out[(size_t)b * HID + h] = h_new;
        out[(size_t)BATCH * HID + (size_t)b * HID + h] = c_new;
    }
}

// ---------------- launch ----------------
extern "C" void kernel_launch(void* const* d_in, const int* in_sizes, int n_in,
                              void* d_out, int out_size) {
    const float* input = (const float*)d_in[0];
    const float* hx    = (const float*)d_in[1];
    const float* cx    = (const float*)d_in[2];
    const float* Wi    = (const float*)d_in[3];
    const float* bi    = (const float*)d_in[4];
    const float* Wf    = (const float*)d_in[5];
    const float* bf    = (const float*)d_in[6];
    const float* Wg    = (const float*)d_in[7];
    const float* bg    = (const float*)d_in[8];
    const float* Wo    = (const float*)d_in[9];
    const float* bo    = (const float*)d_in[10];
    float* out = (float*)d_out;

    static bool attr_set = false;
    if (!attr_set) {
        cudaFuncSetAttribute(lstm_gemm_kernel,
                             cudaFuncAttributeMaxDynamicSharedMemorySize, SMEM_TOTAL);
        attr_set = true;
    }

    {
        int n4 = (BATCH * INF) / 4;
        pack_xh_kernel<<<(n4 + 255) / 256, 256>>>(input, hx);
    }
    {
        int n4 = (GATES * INF) / 4;
        pack_w_kernel<<<(n4 + 255) / 256, 256>>>(Wi, Wf, Wg, Wo);
    }
    {
        dim3 grid(GATES / BN, BATCH / BM);
        lstm_gemm_kernel<<<grid, NTHREADS, SMEM_TOTAL>>>(cx, bi, bf, bg, bo, out);
    }
}